// round 6
// baseline (speedup 1.0000x reference)
#include <cuda_runtime.h>
#include <cuda_bf16.h>
#include <cstdint>

// ---------------------------------------------------------------------------
// AttentionWithCAE: y = proj( attn( x@qkv_w.T + [q_bias,0,v_bias] ) )
// B=8, N=1024, C=768, H=12, hd=64, SCALE=0.125
// Everything on mma.sync bf16 (split hi/lo 3-term, fp32 accumulate).
// R6: 3-stage GEMM pipeline; attention CTA = 128 q-rows / 8 warps.
// ---------------------------------------------------------------------------

#define DIM   768
#define NHEAD 12
#define HD    64
#define BB    8
#define NN_   1024
#define MTOT  (BB * NN_)          // 8192
#define QKSCALE 0.125f
#define K2    (3 * DIM)           // 2304 expanded K
#define NC64  (K2 / 64)           // 36 K-chunks of 64
#define BHTOT (BB * NHEAD)        // 96

// scratch (device globals; no allocations allowed)
__device__ unsigned char g_mask[BB * NN_];
__device__ __nv_bfloat16 g_xs[MTOT * K2];        // x split     [Ah,Ah,Al]
__device__ __nv_bfloat16 g_ws[3 * DIM * K2];     // qkv_w split [Bh,Bl,Bh]
__device__ __nv_bfloat16 g_as[MTOT * K2];        // attn out split [hi,hi,lo]
__device__ __nv_bfloat16 g_ps[DIM * K2];         // proj_w split

// q/k/v bf16 hi/lo planes, layout [bh][n][64]
__device__ __nv_bfloat16 g_qh[BHTOT * NN_ * HD];
__device__ __nv_bfloat16 g_ql[BHTOT * NN_ * HD];
__device__ __nv_bfloat16 g_kh[BHTOT * NN_ * HD];
__device__ __nv_bfloat16 g_kl[BHTOT * NN_ * HD];
__device__ __nv_bfloat16 g_vh[BHTOT * NN_ * HD];
__device__ __nv_bfloat16 g_vl[BHTOT * NN_ * HD];

// ---------------------------------------------------------------------------
// helpers
// ---------------------------------------------------------------------------
__device__ __forceinline__ uint32_t smem_u32(const void* p) {
    uint32_t a;
    asm("{ .reg .u64 t; cvta.to.shared.u64 t, %1; cvt.u32.u64 %0, t; }"
        : "=r"(a) : "l"(p));
    return a;
}
#define SW128(o) ((o) ^ (((o) >> 3) & 0x70))

#define CP_ASYNC16(dst, src) \
    asm volatile("cp.async.cg.shared.global [%0], [%1], 16;" \
                 :: "r"(dst), "l"(src) : "memory")
#define CP_COMMIT() asm volatile("cp.async.commit_group;" ::: "memory")
#define CP_WAIT0()  asm volatile("cp.async.wait_group 0;" ::: "memory")
#define CP_WAIT1()  asm volatile("cp.async.wait_group 1;" ::: "memory")

__device__ __forceinline__ void ldsm4(uint32_t* r, uint32_t addr) {
    asm volatile("ldmatrix.sync.aligned.m8n8.x4.shared.b16 {%0,%1,%2,%3}, [%4];"
        : "=r"(r[0]), "=r"(r[1]), "=r"(r[2]), "=r"(r[3]) : "r"(addr));
}
__device__ __forceinline__ void ldsm4t(uint32_t* r, uint32_t addr) {
    asm volatile("ldmatrix.sync.aligned.m8n8.x4.trans.shared.b16 {%0,%1,%2,%3}, [%4];"
        : "=r"(r[0]), "=r"(r[1]), "=r"(r[2]), "=r"(r[3]) : "r"(addr));
}
__device__ __forceinline__ void mma16816(float* d, const uint32_t* a,
                                         const uint32_t* b) {
    asm volatile(
        "mma.sync.aligned.m16n8k16.row.col.f32.bf16.bf16.f32 "
        "{%0,%1,%2,%3}, {%4,%5,%6,%7}, {%8,%9}, {%0,%1,%2,%3};"
        : "+f"(d[0]), "+f"(d[1]), "+f"(d[2]), "+f"(d[3])
        : "r"(a[0]), "r"(a[1]), "r"(a[2]), "r"(a[3]), "r"(b[0]), "r"(b[1]));
}
__device__ __forceinline__ uint32_t packbf(float x, float y) {
    __nv_bfloat162 t = __floats2bfloat162_rn(x, y);
    return *(uint32_t*)&t;
}

// ---------------------------------------------------------------------------
// mask canonicalization (handles bool/int32/f32 payloads)
// ---------------------------------------------------------------------------
__global__ void mask_canon_kernel(const unsigned char* __restrict__ raw) {
    __shared__ int s_mis, s_notf, s_one;
    if (threadIdx.x == 0) { s_mis = 0; s_notf = 0; s_one = 0; }
    __syncthreads();
    int mis = 0, notf = 0, one = 0;
    const int* ri = (const int*)raw;
    for (int i = threadIdx.x; i < MTOT; i += blockDim.x)
        if ((i & 3) != 0 && raw[i] != 0) mis = 1;
    for (int i = threadIdx.x; i < MTOT / 4; i += blockDim.x) {
        int v = ri[i];
        if (v == 0x3f800000) one = 1; else if (v != 0) notf = 1;
    }
    if (mis)  atomicOr(&s_mis, 1);
    if (notf) atomicOr(&s_notf, 1);
    if (one)  atomicOr(&s_one, 1);
    __syncthreads();
    int is_f32 = (!s_notf) && s_one;
    int is_i32 = (!is_f32) && (!s_mis);
    for (int i = threadIdx.x; i < MTOT; i += blockDim.x) {
        unsigned char m;
        if (is_f32)      m = (((const float*)raw)[i] != 0.0f) ? 1 : 0;
        else if (is_i32) m = (((const int*)raw)[i]   != 0)    ? 1 : 0;
        else             m = (raw[i] != 0) ? 1 : 0;
        g_mask[i] = m;
    }
}

// ---------------------------------------------------------------------------
// split conversion: src[rows][768] f32 -> dst[rows][2304] bf16
// pattern 0 (A side): [hi, hi, lo] ; pattern 1 (B side): [hi, lo, hi]
// ---------------------------------------------------------------------------
template <int PAT>
__global__ void split_kernel(const float* __restrict__ src,
                             __nv_bfloat16* __restrict__ dst, int total) {
    int i = blockIdx.x * blockDim.x + threadIdx.x;
    if (i >= total) return;
    int m = i / DIM, k = i % DIM;
    float v = src[i];
    __nv_bfloat16 h = __float2bfloat16(v);
    __nv_bfloat16 l = __float2bfloat16(v - __bfloat162float(h));
    size_t base = (size_t)m * K2 + k;
    if (PAT == 0) { dst[base] = h; dst[base + DIM] = h; dst[base + 2 * DIM] = l; }
    else          { dst[base] = h; dst[base + DIM] = l; dst[base + 2 * DIM] = h; }
}

// ---------------------------------------------------------------------------
// mma.sync GEMM: C[M, Ntot] = A'[M,2304] @ B'[Ntot,2304]^T
// 3-stage cp.async pipeline, one __syncthreads per K-chunk.
// MODE 0: out = C + bias_b[n]                         (projection)
// MODE 1: split-scatter to q/k/v hi-lo planes (+biases, q*scale)
// ---------------------------------------------------------------------------
#define TILE16K  16384
#define STAGE_B  (2 * TILE16K)
#define GEMM_DSMEM (3 * STAGE_B)       // 98304

template <int MODE>
__global__ __launch_bounds__(256, 1) void mma_gemm_kernel(
    const __nv_bfloat16* __restrict__ A2, const __nv_bfloat16* __restrict__ B2,
    const float* __restrict__ bias_a, const float* __restrict__ bias_b,
    float* __restrict__ out, int Ntot)
{
    extern __shared__ char sm[];
    const int tid  = threadIdx.x;
    const int lane = tid & 31;
    const int wid  = tid >> 5;
    const int wm   = wid & 3;
    const int wn   = wid >> 2;
    const int m0 = blockIdx.y * 128;
    const int n0 = blockIdx.x * 128;

    float acc[2][8][4];
#pragma unroll
    for (int a = 0; a < 2; a++)
#pragma unroll
        for (int b = 0; b < 8; b++)
#pragma unroll
            for (int c = 0; c < 4; c++) acc[a][b][c] = 0.f;

    auto load_tiles = [&](int kt, int s) {
        char* sa = sm + s * STAGE_B;
        char* sb = sa + TILE16K;
        const int k0 = kt * 64;
#pragma unroll
        for (int i = 0; i < 4; i++) {
            int idx = i * 256 + tid;
            int r = idx >> 3, ch = idx & 7;
            uint32_t dst = smem_u32(sa + SW128((uint32_t)(r * 128 + ch * 16)));
            CP_ASYNC16(dst, A2 + (size_t)(m0 + r) * K2 + k0 + ch * 8);
        }
#pragma unroll
        for (int i = 0; i < 4; i++) {
            int idx = i * 256 + tid;
            int r = idx >> 3, ch = idx & 7;
            uint32_t dst = smem_u32(sb + SW128((uint32_t)(r * 128 + ch * 16)));
            CP_ASYNC16(dst, B2 + (size_t)(n0 + r) * K2 + k0 + ch * 8);
        }
    };

    load_tiles(0, 0); CP_COMMIT();
    load_tiles(1, 1); CP_COMMIT();

    for (int kt = 0; kt < NC64; kt++) {
        const int s = kt % 3;
        if (kt + 1 < NC64) CP_WAIT1(); else CP_WAIT0();
        __syncthreads();
        if (kt + 2 < NC64) { load_tiles(kt + 2, (kt + 2) % 3); CP_COMMIT(); }

        const uint32_t a_base = smem_u32(sm + s * STAGE_B);
        const uint32_t b_base = a_base + TILE16K;
#pragma unroll
        for (int ks = 0; ks < 4; ks++) {
            uint32_t afr[2][4];
#pragma unroll
            for (int mt = 0; mt < 2; mt++) {
                int row = wm * 32 + mt * 16 + (lane & 15);
                uint32_t off = SW128((uint32_t)(row * 128 + ks * 32
                                                + ((lane >> 4) << 4)));
                ldsm4(afr[mt], a_base + off);
            }
            uint32_t bfr[4][4];
#pragma unroll
            for (int p = 0; p < 4; p++) {
                int row = wn * 64 + p * 16 + ((lane >> 4) << 3) + (lane & 7);
                uint32_t off = SW128((uint32_t)(row * 128 + ks * 32
                                                + (((lane >> 3) & 1) << 4)));
                ldsm4(bfr[p], b_base + off);
            }
#pragma unroll
            for (int mt = 0; mt < 2; mt++)
#pragma unroll
                for (int p = 0; p < 4; p++) {
                    mma16816(acc[mt][2 * p + 0], afr[mt], &bfr[p][0]);
                    mma16816(acc[mt][2 * p + 1], afr[mt], &bfr[p][2]);
                }
        }
    }

    // epilogue straight from registers
#pragma unroll
    for (int mt = 0; mt < 2; mt++) {
#pragma unroll
        for (int nt = 0; nt < 8; nt++) {
            int rb = m0 + wm * 32 + mt * 16 + (lane >> 2);
            int cb = n0 + wn * 64 + nt * 8 + ((lane & 3) << 1);
#pragma unroll
            for (int h2 = 0; h2 < 2; h2++) {
                int m = rb + h2 * 8;
                float v0 = acc[mt][nt][h2 * 2 + 0];
                float v1 = acc[mt][nt][h2 * 2 + 1];
                if (MODE == 0) {
                    float2 o = make_float2(v0 + bias_b[cb], v1 + bias_b[cb + 1]);
                    *(float2*)&out[(size_t)m * Ntot + cb] = o;
                } else {
                    int which = cb / DIM;
                    int cc = cb - which * DIM;
                    int h = cc >> 6, d = cc & 63;
                    int b = m >> 10, nn = m & 1023;
                    size_t dst = ((size_t)(b * NHEAD + h) * NN_ + nn) * HD + d;
                    if (which == 0) { v0 = (v0 + bias_a[cc]) * QKSCALE;
                                      v1 = (v1 + bias_a[cc + 1]) * QKSCALE; }
                    else if (which == 2) { v0 += bias_b[cc]; v1 += bias_b[cc + 1]; }
                    __nv_bfloat16 h0 = __float2bfloat16(v0);
                    __nv_bfloat16 h1 = __float2bfloat16(v1);
                    uint32_t lop = packbf(v0 - __bfloat162float(h0),
                                          v1 - __bfloat162float(h1));
                    uint32_t hp; { __nv_bfloat162 t; t.x = h0; t.y = h1;
                                   hp = *(uint32_t*)&t; }
                    __nv_bfloat16* ph; __nv_bfloat16* pl;
                    if (which == 0)      { ph = g_qh; pl = g_ql; }
                    else if (which == 1) { ph = g_kh; pl = g_kl; }
                    else                 { ph = g_vh; pl = g_vl; }
                    *(uint32_t*)&ph[dst] = hp;
                    *(uint32_t*)&pl[dst] = lop;
                }
            }
        }
    }
}

// ---------------------------------------------------------------------------
// Tensor-core flash attention.
// CTA: 128 q-rows x 1 head, 8 warps (16 rows each). Key tile = 64.
// S = Qh*Kh + Qh*Kl + Ql*Kh ; P split hi/lo ; O += Ph*Vh + Ph*Vl + Pl*Vh.
// smem: 2 stages x {Kh,Kl,Vh,Vl}[64][128B swizzled] = 65536 B dynamic.
// Q (hi+lo, 32KB) staged through stage-0 area before the mainloop.
// ---------------------------------------------------------------------------
#define KT 64
#define NKT (NN_ / KT)             // 16
#define ASTAGE 32768
#define ATTN_DSMEM (2 * ASTAGE)

__global__ __launch_bounds__(256) void attn_mma_kernel() {
    extern __shared__ char sm[];
    __shared__ float Ms[2][KT];

    const int tid  = threadIdx.x;
    const int lane = tid & 31;
    const int warp = tid >> 5;
    const int q0 = blockIdx.x * 128;
    const int bh = blockIdx.y;
    const int b  = bh / NHEAD;
    const size_t hbase = (size_t)bh * NN_ * HD;

    const __nv_bfloat16* qh_g = g_qh + hbase;
    const __nv_bfloat16* ql_g = g_ql + hbase;
    const __nv_bfloat16* kh_g = g_kh + hbase;
    const __nv_bfloat16* kl_g = g_kl + hbase;
    const __nv_bfloat16* vh_g = g_vh + hbase;
    const __nv_bfloat16* vl_g = g_vl + hbase;

    // ---- stage Q (hi,lo): 128 rows x 128B per plane = 16KB each ----
#pragma unroll
    for (int i = 0; i < 8; i++) {
        int idx = i * 256 + tid;               // 0..2047
        int arr = idx >> 10;                   // 0 hi, 1 lo
        int r = (idx >> 3) & 127, c = idx & 7;
        const __nv_bfloat16* src = (arr ? ql_g : qh_g) + (size_t)(q0 + r) * HD + c * 8;
        uint32_t dst = smem_u32(sm + arr * 16384 + SW128((uint32_t)(r * 128 + c * 16)));
        CP_ASYNC16(dst, src);
    }
    CP_COMMIT(); CP_WAIT0();
    __syncthreads();

    uint32_t qfh[4][4], qfl[4][4];
#pragma unroll
    for (int s = 0; s < 4; s++) {
        int row = warp * 16 + (lane & 15);
        uint32_t off = SW128((uint32_t)(row * 128 + s * 32 + ((lane >> 4) << 4)));
        ldsm4(qfh[s], smem_u32(sm) + off);
        ldsm4(qfl[s], smem_u32(sm) + 16384 + off);
    }
    __syncthreads();

    auto load_kv = [&](int t, int s) {
        int k0 = t * KT;
        char* st = sm + s * ASTAGE;
#pragma unroll
        for (int i = 0; i < 8; i++) {
            int idx = i * 256 + tid;           // 0..2047
            int arr = idx >> 9;                // 0 kh, 1 kl, 2 vh, 3 vl
            int r = (idx >> 3) & 63, c = idx & 7;
            const __nv_bfloat16* bsrc =
                (arr == 0) ? kh_g : (arr == 1) ? kl_g : (arr == 2) ? vh_g : vl_g;
            uint32_t dst = smem_u32(st + arr * 8192 + SW128((uint32_t)(r * 128 + c * 16)));
            CP_ASYNC16(dst, bsrc + (size_t)(k0 + r) * HD + c * 8);
        }
        if (tid < KT)
            Ms[s][tid] = g_mask[b * NN_ + k0 + tid] ? -1e30f : 0.f;
    };

    float m_[2] = {-1e30f, -1e30f};
    float l_[2] = {0.f, 0.f};
    float Oa[8][4];
#pragma unroll
    for (int j = 0; j < 8; j++)
#pragma unroll
        for (int c = 0; c < 4; c++) Oa[j][c] = 0.f;

    load_kv(0, 0);
    CP_COMMIT();

    for (int t = 0; t < NKT; t++) {
        const int s = t & 1;
        if (t + 1 < NKT) { load_kv(t + 1, s ^ 1); CP_COMMIT(); CP_WAIT1(); }
        else             { CP_WAIT0(); }
        __syncthreads();

        const uint32_t kh_b = smem_u32(sm + s * ASTAGE);
        const uint32_t kl_b = kh_b + 8192;
        const uint32_t vh_b = kh_b + 16384;
        const uint32_t vl_b = kh_b + 24576;

        // ---- S = Q K^T (3-term) ----
        float Sa[8][4];
#pragma unroll
        for (int j = 0; j < 8; j++)
#pragma unroll
            for (int c = 0; c < 4; c++) Sa[j][c] = 0.f;

#pragma unroll
        for (int sk = 0; sk < 4; sk++) {
            uint32_t bhf[4][4], blf[4][4];
#pragma unroll
            for (int p = 0; p < 4; p++) {
                int row = p * 16 + ((lane >> 4) << 3) + (lane & 7);
                uint32_t off = SW128((uint32_t)(row * 128 + sk * 32
                                                + (((lane >> 3) & 1) << 4)));
                ldsm4(bhf[p], kh_b + off);
                ldsm4(blf[p], kl_b + off);
            }
#pragma unroll
            for (int p = 0; p < 4; p++) {
                mma16816(Sa[2 * p + 0], qfh[sk], &bhf[p][0]);
                mma16816(Sa[2 * p + 1], qfh[sk], &bhf[p][2]);
                mma16816(Sa[2 * p + 0], qfh[sk], &blf[p][0]);
                mma16816(Sa[2 * p + 1], qfh[sk], &blf[p][2]);
                mma16816(Sa[2 * p + 0], qfl[sk], &bhf[p][0]);
                mma16816(Sa[2 * p + 1], qfl[sk], &bhf[p][2]);
            }
        }

        // ---- mask + online softmax ----
        const int cb = (lane & 3) << 1;
#pragma unroll
        for (int j = 0; j < 8; j++) {
            float2 ma = *(float2*)&Ms[s][j * 8 + cb];
            Sa[j][0] += ma.x; Sa[j][1] += ma.y;
            Sa[j][2] += ma.x; Sa[j][3] += ma.y;
        }
#pragma unroll
        for (int h = 0; h < 2; h++) {
            float mx = -1e30f;
#pragma unroll
            for (int j = 0; j < 8; j++)
                mx = fmaxf(mx, fmaxf(Sa[j][2 * h], Sa[j][2 * h + 1]));
            mx = fmaxf(mx, __shfl_xor_sync(0xffffffffu, mx, 1));
            mx = fmaxf(mx, __shfl_xor_sync(0xffffffffu, mx, 2));
            float mn = fmaxf(m_[h], mx);
            float corr = __expf(m_[h] - mn);
            m_[h] = mn;
            float rs = 0.f;
#pragma unroll
            for (int j = 0; j < 8; j++) {
                Sa[j][2 * h]     = __expf(Sa[j][2 * h]     - mn);
                Sa[j][2 * h + 1] = __expf(Sa[j][2 * h + 1] - mn);
                rs += Sa[j][2 * h] + Sa[j][2 * h + 1];
            }
            rs += __shfl_xor_sync(0xffffffffu, rs, 1);
            rs += __shfl_xor_sync(0xffffffffu, rs, 2);
            l_[h] = l_[h] * corr + rs;
#pragma unroll
            for (int j = 0; j < 8; j++) {
                Oa[j][2 * h]     *= corr;
                Oa[j][2 * h + 1] *= corr;
            }
        }

        // ---- O += P V (3-term), P repacked from S fragments ----
#pragma unroll
        for (int k2 = 0; k2 < 4; k2++) {
            uint32_t pah[4], pal[4];
#pragma unroll
            for (int u = 0; u < 2; u++) {
                int j = 2 * k2 + u;
                float p0 = Sa[j][0], p1 = Sa[j][1];
                float p2 = Sa[j][2], p3 = Sa[j][3];
                __nv_bfloat16 h0 = __float2bfloat16(p0), h1 = __float2bfloat16(p1);
                __nv_bfloat16 h2 = __float2bfloat16(p2), h3 = __float2bfloat16(p3);
                __nv_bfloat162 t0; t0.x = h0; t0.y = h1;
                __nv_bfloat162 t1; t1.x = h2; t1.y = h3;
                pah[u]     = *(uint32_t*)&t0;
                pah[u + 2] = *(uint32_t*)&t1;
                pal[u]     = packbf(p0 - __bfloat162float(h0),
                                    p1 - __bfloat162float(h1));
                pal[u + 2] = packbf(p2 - __bfloat162float(h2),
                                    p3 - __bfloat162float(h3));
            }
            // reorder to mma A-frag: {m0-7 k0-7, m8-15 k0-7, m0-7 k8-15, m8-15 k8-15}
            uint32_t pahf[4] = {pah[0], pah[2], pah[1], pah[3]};
            uint32_t palf[4] = {pal[0], pal[2], pal[1], pal[3]};
            uint32_t bvh[4][4], bvl[4][4];
#pragma unroll
            for (int p = 0; p < 4; p++) {
                int row = k2 * 16 + (lane & 15);
                uint32_t off = SW128((uint32_t)(row * 128 + p * 32
                                                + ((lane >> 4) << 4)));
                ldsm4t(bvh[p], vh_b + off);
                ldsm4t(bvl[p], vl_b + off);
            }
#pragma unroll
            for (int p = 0; p < 4; p++) {
                mma16816(Oa[2 * p + 0], pahf, &bvh[p][0]);
                mma16816(Oa[2 * p + 1], pahf, &bvh[p][2]);
                mma16816(Oa[2 * p + 0], pahf, &bvl[p][0]);
                mma16816(Oa[2 * p + 1], pahf, &bvl[p][2]);
                mma16816(Oa[2 * p + 0], palf, &bvh[p][0]);
                mma16816(Oa[2 * p + 1], palf, &bvh[p][2]);
            }
        }
        __syncthreads();
    }

    // ---- epilogue: normalize, split, write g_as ([hi,hi,lo] @ k,768+k,1536+k)
    const int hcol = (bh % NHEAD) * HD;
#pragma unroll
    for (int h = 0; h < 2; h++) {
        float inv = 1.f / l_[h];
        int row = q0 + warp * 16 + (lane >> 2) + h * 8;
        size_t mrow = (size_t)(b * NN_ + row) * K2;
#pragma unroll
        for (int j = 0; j < 8; j++) {
            int col = hcol + j * 8 + ((lane & 3) << 1);
            float v0 = Oa[j][2 * h] * inv;
            float v1 = Oa[j][2 * h + 1] * inv;
            __nv_bfloat16 h0 = __float2bfloat16(v0);
            __nv_bfloat16 h1 = __float2bfloat16(v1);
            __nv_bfloat162 hp; hp.x = h0; hp.y = h1;
            uint32_t lop = packbf(v0 - __bfloat162float(h0),
                                  v1 - __bfloat162float(h1));
            *(uint32_t*)&g_as[mrow + col]            = *(uint32_t*)&hp;
            *(uint32_t*)&g_as[mrow + DIM + col]      = *(uint32_t*)&hp;
            *(uint32_t*)&g_as[mrow + 2 * DIM + col]  = lop;
        }
    }
}

// ---------------------------------------------------------------------------
// launch
// ---------------------------------------------------------------------------
extern "C" void kernel_launch(void* const* d_in, const int* in_sizes, int n_in,
                              void* d_out, int out_size) {
    const float* x      = (const float*)d_in[0];
    const unsigned char* mask_raw = (const unsigned char*)d_in[1];
    const float* qkv_w  = (const float*)d_in[2];
    const float* q_bias = (const float*)d_in[3];
    const float* v_bias = (const float*)d_in[4];
    const float* proj_w = (const float*)d_in[5];
    const float* proj_b = (const float*)d_in[6];
    float* out          = (float*)d_out;
    (void)in_sizes; (void)n_in; (void)out_size;

    cudaFuncSetAttribute(mma_gemm_kernel<0>,
                         cudaFuncAttributeMaxDynamicSharedMemorySize, GEMM_DSMEM);
    cudaFuncSetAttribute(mma_gemm_kernel<1>,
                         cudaFuncAttributeMaxDynamicSharedMemorySize, GEMM_DSMEM);
    cudaFuncSetAttribute(attn_mma_kernel,
                         cudaFuncAttributeMaxDynamicSharedMemorySize, ATTN_DSMEM);

    __nv_bfloat16 *xs = nullptr, *ws = nullptr, *as = nullptr, *ps = nullptr;
    cudaGetSymbolAddress((void**)&xs, g_xs);
    cudaGetSymbolAddress((void**)&ws, g_ws);
    cudaGetSymbolAddress((void**)&as, g_as);
    cudaGetSymbolAddress((void**)&ps, g_ps);

    // 1) mask
    mask_canon_kernel<<<1, 256>>>(mask_raw);

    // 2) split conversions (x, qkv_w, proj_w)
    {
        int tA = MTOT * DIM;
        split_kernel<0><<<(tA + 255) / 256, 256>>>(x, xs, tA);
        int tB = 3 * DIM * DIM;
        split_kernel<1><<<(tB + 255) / 256, 256>>>(qkv_w, ws, tB);
        int tP = DIM * DIM;
        split_kernel<1><<<(tP + 255) / 256, 256>>>(proj_w, ps, tP);
    }

    // 3) QKV GEMM -> q/k/v bf16 hi-lo planes
    mma_gemm_kernel<1><<<dim3(3 * DIM / 128, MTOT / 128), 256, GEMM_DSMEM>>>(
        xs, ws, q_bias, v_bias, nullptr, 3 * DIM);

    // 4) tensor-core attention -> g_as (pre-split proj input)
    attn_mma_kernel<<<dim3(NN_ / 128, BHTOT), 256, ATTN_DSMEM>>>();

    // 5) projection GEMM: [8192 x 768]
    mma_gemm_kernel<0><<<dim3(DIM / 128, MTOT / 128), 256, GEMM_DSMEM>>>(
        as, ps, nullptr, proj_b, out, DIM);
}

// round 10
// speedup vs baseline: 1.2405x; 1.2405x over previous
#include <cuda_runtime.h>
#include <cuda_bf16.h>
#include <cstdint>

// ---------------------------------------------------------------------------
// AttentionWithCAE: y = proj( attn( x@qkv_w.T + [q_bias,0,v_bias] ) )
// B=8, N=1024, C=768, H=12, hd=64, SCALE=0.125
// Everything on mma.sync bf16 (split hi/lo 3-term, fp32 accumulate).
// R10 = R7 resubmit (3x infra timeout): GEMM __launch_bounds__(256,2).
// ---------------------------------------------------------------------------

#define DIM   768
#define NHEAD 12
#define HD    64
#define BB    8
#define NN_   1024
#define MTOT  (BB * NN_)          // 8192
#define QKSCALE 0.125f
#define K2    (3 * DIM)           // 2304 expanded K
#define NC64  (K2 / 64)           // 36 K-chunks of 64
#define BHTOT (BB * NHEAD)        // 96

// scratch (device globals; no allocations allowed)
__device__ unsigned char g_mask[BB * NN_];
__device__ __nv_bfloat16 g_xs[MTOT * K2];        // x split     [Ah,Ah,Al]
__device__ __nv_bfloat16 g_ws[3 * DIM * K2];     // qkv_w split [Bh,Bl,Bh]
__device__ __nv_bfloat16 g_as[MTOT * K2];        // attn out split [hi,hi,lo]
__device__ __nv_bfloat16 g_ps[DIM * K2];         // proj_w split

// q/k/v bf16 hi/lo planes, layout [bh][n][64]
__device__ __nv_bfloat16 g_qh[BHTOT * NN_ * HD];
__device__ __nv_bfloat16 g_ql[BHTOT * NN_ * HD];
__device__ __nv_bfloat16 g_kh[BHTOT * NN_ * HD];
__device__ __nv_bfloat16 g_kl[BHTOT * NN_ * HD];
__device__ __nv_bfloat16 g_vh[BHTOT * NN_ * HD];
__device__ __nv_bfloat16 g_vl[BHTOT * NN_ * HD];

// ---------------------------------------------------------------------------
// helpers
// ---------------------------------------------------------------------------
__device__ __forceinline__ uint32_t smem_u32(const void* p) {
    uint32_t a;
    asm("{ .reg .u64 t; cvta.to.shared.u64 t, %1; cvt.u32.u64 %0, t; }"
        : "=r"(a) : "l"(p));
    return a;
}
#define SW128(o) ((o) ^ (((o) >> 3) & 0x70))

#define CP_ASYNC16(dst, src) \
    asm volatile("cp.async.cg.shared.global [%0], [%1], 16;" \
                 :: "r"(dst), "l"(src) : "memory")
#define CP_COMMIT() asm volatile("cp.async.commit_group;" ::: "memory")
#define CP_WAIT0()  asm volatile("cp.async.wait_group 0;" ::: "memory")
#define CP_WAIT1()  asm volatile("cp.async.wait_group 1;" ::: "memory")

__device__ __forceinline__ void ldsm4(uint32_t* r, uint32_t addr) {
    asm volatile("ldmatrix.sync.aligned.m8n8.x4.shared.b16 {%0,%1,%2,%3}, [%4];"
        : "=r"(r[0]), "=r"(r[1]), "=r"(r[2]), "=r"(r[3]) : "r"(addr));
}
__device__ __forceinline__ void ldsm4t(uint32_t* r, uint32_t addr) {
    asm volatile("ldmatrix.sync.aligned.m8n8.x4.trans.shared.b16 {%0,%1,%2,%3}, [%4];"
        : "=r"(r[0]), "=r"(r[1]), "=r"(r[2]), "=r"(r[3]) : "r"(addr));
}
__device__ __forceinline__ void mma16816(float* d, const uint32_t* a,
                                         const uint32_t* b) {
    asm volatile(
        "mma.sync.aligned.m16n8k16.row.col.f32.bf16.bf16.f32 "
        "{%0,%1,%2,%3}, {%4,%5,%6,%7}, {%8,%9}, {%0,%1,%2,%3};"
        : "+f"(d[0]), "+f"(d[1]), "+f"(d[2]), "+f"(d[3])
        : "r"(a[0]), "r"(a[1]), "r"(a[2]), "r"(a[3]), "r"(b[0]), "r"(b[1]));
}
__device__ __forceinline__ uint32_t packbf(float x, float y) {
    __nv_bfloat162 t = __floats2bfloat162_rn(x, y);
    return *(uint32_t*)&t;
}

// ---------------------------------------------------------------------------
// mask canonicalization (handles bool/int32/f32 payloads)
// ---------------------------------------------------------------------------
__global__ void mask_canon_kernel(const unsigned char* __restrict__ raw) {
    __shared__ int s_mis, s_notf, s_one;
    if (threadIdx.x == 0) { s_mis = 0; s_notf = 0; s_one = 0; }
    __syncthreads();
    int mis = 0, notf = 0, one = 0;
    const int* ri = (const int*)raw;
    for (int i = threadIdx.x; i < MTOT; i += blockDim.x)
        if ((i & 3) != 0 && raw[i] != 0) mis = 1;
    for (int i = threadIdx.x; i < MTOT / 4; i += blockDim.x) {
        int v = ri[i];
        if (v == 0x3f800000) one = 1; else if (v != 0) notf = 1;
    }
    if (mis)  atomicOr(&s_mis, 1);
    if (notf) atomicOr(&s_notf, 1);
    if (one)  atomicOr(&s_one, 1);
    __syncthreads();
    int is_f32 = (!s_notf) && s_one;
    int is_i32 = (!is_f32) && (!s_mis);
    for (int i = threadIdx.x; i < MTOT; i += blockDim.x) {
        unsigned char m;
        if (is_f32)      m = (((const float*)raw)[i] != 0.0f) ? 1 : 0;
        else if (is_i32) m = (((const int*)raw)[i]   != 0)    ? 1 : 0;
        else             m = (raw[i] != 0) ? 1 : 0;
        g_mask[i] = m;
    }
}

// ---------------------------------------------------------------------------
// split conversion: src[rows][768] f32 -> dst[rows][2304] bf16
// pattern 0 (A side): [hi, hi, lo] ; pattern 1 (B side): [hi, lo, hi]
// ---------------------------------------------------------------------------
template <int PAT>
__global__ void split_kernel(const float* __restrict__ src,
                             __nv_bfloat16* __restrict__ dst, int total) {
    int i = blockIdx.x * blockDim.x + threadIdx.x;
    if (i >= total) return;
    int m = i / DIM, k = i % DIM;
    float v = src[i];
    __nv_bfloat16 h = __float2bfloat16(v);
    __nv_bfloat16 l = __float2bfloat16(v - __bfloat162float(h));
    size_t base = (size_t)m * K2 + k;
    if (PAT == 0) { dst[base] = h; dst[base + DIM] = h; dst[base + 2 * DIM] = l; }
    else          { dst[base] = h; dst[base + DIM] = l; dst[base + 2 * DIM] = h; }
}

// ---------------------------------------------------------------------------
// mma.sync GEMM: C[M, Ntot] = A'[M,2304] @ B'[Ntot,2304]^T
// 2-stage cp.async pipeline, 2 CTAs/SM (regs capped at 128).
// MODE 0: out = C + bias_b[n]                         (projection)
// MODE 1: split-scatter to q/k/v hi-lo planes (+biases, q*scale)
// ---------------------------------------------------------------------------
#define TILE16K  16384
#define STAGE_B  (2 * TILE16K)
#define GEMM_DSMEM (2 * STAGE_B)       // 65536

template <int MODE>
__global__ __launch_bounds__(256, 2) void mma_gemm_kernel(
    const __nv_bfloat16* __restrict__ A2, const __nv_bfloat16* __restrict__ B2,
    const float* __restrict__ bias_a, const float* __restrict__ bias_b,
    float* __restrict__ out, int Ntot)
{
    extern __shared__ char sm[];
    const int tid  = threadIdx.x;
    const int lane = tid & 31;
    const int wid  = tid >> 5;
    const int wm   = wid & 3;
    const int wn   = wid >> 2;
    const int m0 = blockIdx.y * 128;
    const int n0 = blockIdx.x * 128;

    float acc[2][8][4];
#pragma unroll
    for (int a = 0; a < 2; a++)
#pragma unroll
        for (int b = 0; b < 8; b++)
#pragma unroll
            for (int c = 0; c < 4; c++) acc[a][b][c] = 0.f;

    auto load_tiles = [&](int kt, int s) {
        char* sa = sm + s * STAGE_B;
        char* sb = sa + TILE16K;
        const int k0 = kt * 64;
#pragma unroll
        for (int i = 0; i < 4; i++) {
            int idx = i * 256 + tid;
            int r = idx >> 3, ch = idx & 7;
            uint32_t dst = smem_u32(sa + SW128((uint32_t)(r * 128 + ch * 16)));
            CP_ASYNC16(dst, A2 + (size_t)(m0 + r) * K2 + k0 + ch * 8);
        }
#pragma unroll
        for (int i = 0; i < 4; i++) {
            int idx = i * 256 + tid;
            int r = idx >> 3, ch = idx & 7;
            uint32_t dst = smem_u32(sb + SW128((uint32_t)(r * 128 + ch * 16)));
            CP_ASYNC16(dst, B2 + (size_t)(n0 + r) * K2 + k0 + ch * 8);
        }
    };

    load_tiles(0, 0);
    CP_COMMIT();

    for (int kt = 0; kt < NC64; kt++) {
        const int s = kt & 1;
        if (kt + 1 < NC64) {
            load_tiles(kt + 1, s ^ 1);
            CP_COMMIT();
            CP_WAIT1();
        } else {
            CP_WAIT0();
        }
        __syncthreads();

        const uint32_t a_base = smem_u32(sm + s * STAGE_B);
        const uint32_t b_base = a_base + TILE16K;
#pragma unroll
        for (int ks = 0; ks < 4; ks++) {
            uint32_t afr[2][4];
#pragma unroll
            for (int mt = 0; mt < 2; mt++) {
                int row = wm * 32 + mt * 16 + (lane & 15);
                uint32_t off = SW128((uint32_t)(row * 128 + ks * 32
                                                + ((lane >> 4) << 4)));
                ldsm4(afr[mt], a_base + off);
            }
            uint32_t bfr[4][4];
#pragma unroll
            for (int p = 0; p < 4; p++) {
                int row = wn * 64 + p * 16 + ((lane >> 4) << 3) + (lane & 7);
                uint32_t off = SW128((uint32_t)(row * 128 + ks * 32
                                                + (((lane >> 3) & 1) << 4)));
                ldsm4(bfr[p], b_base + off);
            }
#pragma unroll
            for (int mt = 0; mt < 2; mt++)
#pragma unroll
                for (int p = 0; p < 4; p++) {
                    mma16816(acc[mt][2 * p + 0], afr[mt], &bfr[p][0]);
                    mma16816(acc[mt][2 * p + 1], afr[mt], &bfr[p][2]);
                }
        }
        __syncthreads();
    }

    // epilogue straight from registers
#pragma unroll
    for (int mt = 0; mt < 2; mt++) {
#pragma unroll
        for (int nt = 0; nt < 8; nt++) {
            int rb = m0 + wm * 32 + mt * 16 + (lane >> 2);
            int cb = n0 + wn * 64 + nt * 8 + ((lane & 3) << 1);
#pragma unroll
            for (int h2 = 0; h2 < 2; h2++) {
                int m = rb + h2 * 8;
                float v0 = acc[mt][nt][h2 * 2 + 0];
                float v1 = acc[mt][nt][h2 * 2 + 1];
                if (MODE == 0) {
                    float2 o = make_float2(v0 + bias_b[cb], v1 + bias_b[cb + 1]);
                    *(float2*)&out[(size_t)m * Ntot + cb] = o;
                } else {
                    int which = cb / DIM;
                    int cc = cb - which * DIM;
                    int h = cc >> 6, d = cc & 63;
                    int b = m >> 10, nn = m & 1023;
                    size_t dst = ((size_t)(b * NHEAD + h) * NN_ + nn) * HD + d;
                    if (which == 0) { v0 = (v0 + bias_a[cc]) * QKSCALE;
                                      v1 = (v1 + bias_a[cc + 1]) * QKSCALE; }
                    else if (which == 2) { v0 += bias_b[cc]; v1 += bias_b[cc + 1]; }
                    __nv_bfloat16 h0 = __float2bfloat16(v0);
                    __nv_bfloat16 h1 = __float2bfloat16(v1);
                    uint32_t lop = packbf(v0 - __bfloat162float(h0),
                                          v1 - __bfloat162float(h1));
                    uint32_t hp; { __nv_bfloat162 t; t.x = h0; t.y = h1;
                                   hp = *(uint32_t*)&t; }
                    __nv_bfloat16* ph; __nv_bfloat16* pl;
                    if (which == 0)      { ph = g_qh; pl = g_ql; }
                    else if (which == 1) { ph = g_kh; pl = g_kl; }
                    else                 { ph = g_vh; pl = g_vl; }
                    *(uint32_t*)&ph[dst] = hp;
                    *(uint32_t*)&pl[dst] = lop;
                }
            }
        }
    }
}

// ---------------------------------------------------------------------------
// Tensor-core flash attention (R5 version).
// CTA: 64 q-rows x 1 head, 4 warps (16 rows each). Key tile = 64.
// S = Qh*Kh + Qh*Kl + Ql*Kh ; P split hi/lo ; O += Ph*Vh + Ph*Vl + Pl*Vh.
// smem: 2 stages x {Kh,Kl,Vh,Vl}[64][128B swizzled] = 65536 B dynamic.
// ---------------------------------------------------------------------------
#define KT 64
#define NKT (NN_ / KT)             // 16
#define ASTAGE 32768
#define ATTN_DSMEM (2 * ASTAGE)

__global__ __launch_bounds__(128) void attn_mma_kernel() {
    extern __shared__ char sm[];
    __shared__ float Ms[2][KT];

    const int tid  = threadIdx.x;
    const int lane = tid & 31;
    const int warp = tid >> 5;
    const int q0 = blockIdx.x * 64;
    const int bh = blockIdx.y;
    const int b  = bh / NHEAD;
    const size_t hbase = (size_t)bh * NN_ * HD;

    const __nv_bfloat16* qh_g = g_qh + hbase;
    const __nv_bfloat16* ql_g = g_ql + hbase;
    const __nv_bfloat16* kh_g = g_kh + hbase;
    const __nv_bfloat16* kl_g = g_kl + hbase;
    const __nv_bfloat16* vh_g = g_vh + hbase;
    const __nv_bfloat16* vl_g = g_vl + hbase;

    // ---- stage Q (hi,lo) through smem, ldmatrix to registers ----
#pragma unroll
    for (int i = 0; i < 8; i++) {
        int idx = i * 128 + tid;               // 0..1023
        int arr = idx >> 9;                    // 0 hi, 1 lo
        int r = (idx >> 3) & 63, c = idx & 7;
        const __nv_bfloat16* src = (arr ? ql_g : qh_g) + (size_t)(q0 + r) * HD + c * 8;
        uint32_t dst = smem_u32(sm + arr * 8192 + SW128((uint32_t)(r * 128 + c * 16)));
        CP_ASYNC16(dst, src);
    }
    CP_COMMIT(); CP_WAIT0();
    __syncthreads();

    uint32_t qfh[4][4], qfl[4][4];
#pragma unroll
    for (int s = 0; s < 4; s++) {
        int row = warp * 16 + (lane & 15);
        uint32_t off = SW128((uint32_t)(row * 128 + s * 32 + ((lane >> 4) << 4)));
        ldsm4(qfh[s], smem_u32(sm) + off);
        ldsm4(qfl[s], smem_u32(sm) + 8192 + off);
    }
    __syncthreads();

    auto load_kv = [&](int t, int s) {
        int k0 = t * KT;
        char* st = sm + s * ASTAGE;
#pragma unroll
        for (int i = 0; i < 16; i++) {
            int idx = i * 128 + tid;           // 0..2047
            int arr = idx >> 9;                // 0 kh, 1 kl, 2 vh, 3 vl
            int r = (idx >> 3) & 63, c = idx & 7;
            const __nv_bfloat16* bsrc =
                (arr == 0) ? kh_g : (arr == 1) ? kl_g : (arr == 2) ? vh_g : vl_g;
            uint32_t dst = smem_u32(st + arr * 8192 + SW128((uint32_t)(r * 128 + c * 16)));
            CP_ASYNC16(dst, bsrc + (size_t)(k0 + r) * HD + c * 8);
        }
        if (tid < KT)
            Ms[s][tid] = g_mask[b * NN_ + k0 + tid] ? -1e30f : 0.f;
    };

    float m_[2] = {-1e30f, -1e30f};
    float l_[2] = {0.f, 0.f};
    float Oa[8][4];
#pragma unroll
    for (int j = 0; j < 8; j++)
#pragma unroll
        for (int c = 0; c < 4; c++) Oa[j][c] = 0.f;

    load_kv(0, 0);
    CP_COMMIT();

    for (int t = 0; t < NKT; t++) {
        const int s = t & 1;
        if (t + 1 < NKT) { load_kv(t + 1, s ^ 1); CP_COMMIT(); CP_WAIT1(); }
        else             { CP_WAIT0(); }
        __syncthreads();

        const uint32_t kh_b = smem_u32(sm + s * ASTAGE);
        const uint32_t kl_b = kh_b + 8192;
        const uint32_t vh_b = kh_b + 16384;
        const uint32_t vl_b = kh_b + 24576;

        // ---- S = Q K^T (3-term) ----
        float Sa[8][4];
#pragma unroll
        for (int j = 0; j < 8; j++)
#pragma unroll
            for (int c = 0; c < 4; c++) Sa[j][c] = 0.f;

#pragma unroll
        for (int sk = 0; sk < 4; sk++) {
            uint32_t bhf[4][4], blf[4][4];
#pragma unroll
            for (int p = 0; p < 4; p++) {
                int row = p * 16 + ((lane >> 4) << 3) + (lane & 7);
                uint32_t off = SW128((uint32_t)(row * 128 + sk * 32
                                                + (((lane >> 3) & 1) << 4)));
                ldsm4(bhf[p], kh_b + off);
                ldsm4(blf[p], kl_b + off);
            }
#pragma unroll
            for (int p = 0; p < 4; p++) {
                mma16816(Sa[2 * p + 0], qfh[sk], &bhf[p][0]);
                mma16816(Sa[2 * p + 1], qfh[sk], &bhf[p][2]);
                mma16816(Sa[2 * p + 0], qfh[sk], &blf[p][0]);
                mma16816(Sa[2 * p + 1], qfh[sk], &blf[p][2]);
                mma16816(Sa[2 * p + 0], qfl[sk], &bhf[p][0]);
                mma16816(Sa[2 * p + 1], qfl[sk], &bhf[p][2]);
            }
        }

        // ---- mask + online softmax ----
        const int cb = (lane & 3) << 1;
#pragma unroll
        for (int j = 0; j < 8; j++) {
            float2 ma = *(float2*)&Ms[s][j * 8 + cb];
            Sa[j][0] += ma.x; Sa[j][1] += ma.y;
            Sa[j][2] += ma.x; Sa[j][3] += ma.y;
        }
#pragma unroll
        for (int h = 0; h < 2; h++) {
            float mx = -1e30f;
#pragma unroll
            for (int j = 0; j < 8; j++)
                mx = fmaxf(mx, fmaxf(Sa[j][2 * h], Sa[j][2 * h + 1]));
            mx = fmaxf(mx, __shfl_xor_sync(0xffffffffu, mx, 1));
            mx = fmaxf(mx, __shfl_xor_sync(0xffffffffu, mx, 2));
            float mn = fmaxf(m_[h], mx);
            float corr = __expf(m_[h] - mn);
            m_[h] = mn;
            float rs = 0.f;
#pragma unroll
            for (int j = 0; j < 8; j++) {
                Sa[j][2 * h]     = __expf(Sa[j][2 * h]     - mn);
                Sa[j][2 * h + 1] = __expf(Sa[j][2 * h + 1] - mn);
                rs += Sa[j][2 * h] + Sa[j][2 * h + 1];
            }
            rs += __shfl_xor_sync(0xffffffffu, rs, 1);
            rs += __shfl_xor_sync(0xffffffffu, rs, 2);
            l_[h] = l_[h] * corr + rs;
#pragma unroll
            for (int j = 0; j < 8; j++) {
                Oa[j][2 * h]     *= corr;
                Oa[j][2 * h + 1] *= corr;
            }
        }

        // ---- O += P V (3-term), P repacked from S fragments ----
#pragma unroll
        for (int k2 = 0; k2 < 4; k2++) {
            uint32_t pah[4], pal[4];
#pragma unroll
            for (int u = 0; u < 2; u++) {
                int j = 2 * k2 + u;
                float p0 = Sa[j][0], p1 = Sa[j][1];
                float p2 = Sa[j][2], p3 = Sa[j][3];
                __nv_bfloat16 h0 = __float2bfloat16(p0), h1 = __float2bfloat16(p1);
                __nv_bfloat16 h2 = __float2bfloat16(p2), h3 = __float2bfloat16(p3);
                __nv_bfloat162 t0; t0.x = h0; t0.y = h1;
                __nv_bfloat162 t1; t1.x = h2; t1.y = h3;
                pah[u]     = *(uint32_t*)&t0;
                pah[u + 2] = *(uint32_t*)&t1;
                pal[u]     = packbf(p0 - __bfloat162float(h0),
                                    p1 - __bfloat162float(h1));
                pal[u + 2] = packbf(p2 - __bfloat162float(h2),
                                    p3 - __bfloat162float(h3));
            }
            // reorder to mma A-frag: {m0-7 k0-7, m8-15 k0-7, m0-7 k8-15, m8-15 k8-15}
            uint32_t pahf[4] = {pah[0], pah[2], pah[1], pah[3]};
            uint32_t palf[4] = {pal[0], pal[2], pal[1], pal[3]};
            uint32_t bvh[4][4], bvl[4][4];
#pragma unroll
            for (int p = 0; p < 4; p++) {
                int row = k2 * 16 + (lane & 15);
                uint32_t off = SW128((uint32_t)(row * 128 + p * 32
                                                + ((lane >> 4) << 4)));
                ldsm4t(bvh[p], vh_b + off);
                ldsm4t(bvl[p], vl_b + off);
            }
#pragma unroll
            for (int p = 0; p < 4; p++) {
                mma16816(Oa[2 * p + 0], pahf, &bvh[p][0]);
                mma16816(Oa[2 * p + 1], pahf, &bvh[p][2]);
                mma16816(Oa[2 * p + 0], pahf, &bvl[p][0]);
                mma16816(Oa[2 * p + 1], pahf, &bvl[p][2]);
                mma16816(Oa[2 * p + 0], palf, &bvh[p][0]);
                mma16816(Oa[2 * p + 1], palf, &bvh[p][2]);
            }
        }
        __syncthreads();
    }

    // ---- epilogue: normalize, split, write g_as ([hi,hi,lo] @ k,768+k,1536+k)
    const int hcol = (bh % NHEAD) * HD;
#pragma unroll
    for (int h = 0; h < 2; h++) {
        float inv = 1.f / l_[h];
        int row = q0 + warp * 16 + (lane >> 2) + h * 8;
        size_t mrow = (size_t)(b * NN_ + row) * K2;
#pragma unroll
        for (int j = 0; j < 8; j++) {
            int col = hcol + j * 8 + ((lane & 3) << 1);
            float v0 = Oa[j][2 * h] * inv;
            float v1 = Oa[j][2 * h + 1] * inv;
            __nv_bfloat16 h0 = __float2bfloat16(v0);
            __nv_bfloat16 h1 = __float2bfloat16(v1);
            __nv_bfloat162 hp; hp.x = h0; hp.y = h1;
            uint32_t lop = packbf(v0 - __bfloat162float(h0),
                                  v1 - __bfloat162float(h1));
            *(uint32_t*)&g_as[mrow + col]            = *(uint32_t*)&hp;
            *(uint32_t*)&g_as[mrow + DIM + col]      = *(uint32_t*)&hp;
            *(uint32_t*)&g_as[mrow + 2 * DIM + col]  = lop;
        }
    }
}

// ---------------------------------------------------------------------------
// launch
// ---------------------------------------------------------------------------
extern "C" void kernel_launch(void* const* d_in, const int* in_sizes, int n_in,
                              void* d_out, int out_size) {
    const float* x      = (const float*)d_in[0];
    const unsigned char* mask_raw = (const unsigned char*)d_in[1];
    const float* qkv_w  = (const float*)d_in[2];
    const float* q_bias = (const float*)d_in[3];
    const float* v_bias = (const float*)d_in[4];
    const float* proj_w = (const float*)d_in[5];
    const float* proj_b = (const float*)d_in[6];
    float* out          = (float*)d_out;
    (void)in_sizes; (void)n_in; (void)out_size;

    cudaFuncSetAttribute(mma_gemm_kernel<0>,
                         cudaFuncAttributeMaxDynamicSharedMemorySize, GEMM_DSMEM);
    cudaFuncSetAttribute(mma_gemm_kernel<1>,
                         cudaFuncAttributeMaxDynamicSharedMemorySize, GEMM_DSMEM);
    cudaFuncSetAttribute(attn_mma_kernel,
                         cudaFuncAttributeMaxDynamicSharedMemorySize, ATTN_DSMEM);

    __nv_bfloat16 *xs = nullptr, *ws = nullptr, *as = nullptr, *ps = nullptr;
    cudaGetSymbolAddress((void**)&xs, g_xs);
    cudaGetSymbolAddress((void**)&ws, g_ws);
    cudaGetSymbolAddress((void**)&as, g_as);
    cudaGetSymbolAddress((void**)&ps, g_ps);

    // 1) mask
    mask_canon_kernel<<<1, 256>>>(mask_raw);

    // 2) split conversions (x, qkv_w, proj_w)
    {
        int tA = MTOT * DIM;
        split_kernel<0><<<(tA + 255) / 256, 256>>>(x, xs, tA);
        int tB = 3 * DIM * DIM;
        split_kernel<1><<<(tB + 255) / 256, 256>>>(qkv_w, ws, tB);
        int tP = DIM * DIM;
        split_kernel<1><<<(tP + 255) / 256, 256>>>(proj_w, ps, tP);
    }

    // 3) QKV GEMM -> q/k/v bf16 hi-lo planes
    mma_gemm_kernel<1><<<dim3(3 * DIM / 128, MTOT / 128), 256, GEMM_DSMEM>>>(
        xs, ws, q_bias, v_bias, nullptr, 3 * DIM);

    // 4) tensor-core attention -> g_as (pre-split proj input)
    attn_mma_kernel<<<dim3(NN_ / 64, BHTOT), 128, ATTN_DSMEM>>>();

    // 5) projection GEMM: [8192 x 768]
    mma_gemm_kernel<0><<<dim3(DIM / 128, MTOT / 128), 256, GEMM_DSMEM>>>(
        as, ps, nullptr, proj_b, out, DIM);
}

// round 14
// speedup vs baseline: 1.5258x; 1.2300x over previous
#include <cuda_runtime.h>
#include <cuda_bf16.h>
#include <cstdint>

// ---------------------------------------------------------------------------
// AttentionWithCAE: y = proj( attn( x@qkv_w.T + [q_bias,0,v_bias] ) )
// B=8, N=1024, C=768, H=12, hd=64, SCALE=0.125
// Everything on mma.sync bf16 (split hi/lo 3-term, fp32 accumulate).
// R14 = R11 resubmit (3x infra timeout): masked-key compaction — attention
// iterates only unmasked keys (~50%), gathered via per-batch index map.
// ---------------------------------------------------------------------------

#define DIM   768
#define NHEAD 12
#define HD    64
#define BB    8
#define NN_   1024
#define MTOT  (BB * NN_)          // 8192
#define QKSCALE 0.125f
#define K2    (3 * DIM)           // 2304 expanded K
#define NC64  (K2 / 64)           // 36 K-chunks of 64
#define BHTOT (BB * NHEAD)        // 96

// scratch (device globals; no allocations allowed)
__device__ int g_idx[BB * NN_];                  // compacted key indices
__device__ int g_cnt[BB];                        // unmasked count per batch
__device__ __nv_bfloat16 g_xs[MTOT * K2];        // x split     [Ah,Ah,Al]
__device__ __nv_bfloat16 g_ws[3 * DIM * K2];     // qkv_w split [Bh,Bl,Bh]
__device__ __nv_bfloat16 g_as[MTOT * K2];        // attn out split [hi,hi,lo]
__device__ __nv_bfloat16 g_ps[DIM * K2];         // proj_w split

// q/k/v bf16 hi/lo planes, layout [bh][n][64]
__device__ __nv_bfloat16 g_qh[BHTOT * NN_ * HD];
__device__ __nv_bfloat16 g_ql[BHTOT * NN_ * HD];
__device__ __nv_bfloat16 g_kh[BHTOT * NN_ * HD];
__device__ __nv_bfloat16 g_kl[BHTOT * NN_ * HD];
__device__ __nv_bfloat16 g_vh[BHTOT * NN_ * HD];
__device__ __nv_bfloat16 g_vl[BHTOT * NN_ * HD];

// ---------------------------------------------------------------------------
// helpers
// ---------------------------------------------------------------------------
__device__ __forceinline__ uint32_t smem_u32(const void* p) {
    uint32_t a;
    asm("{ .reg .u64 t; cvta.to.shared.u64 t, %1; cvt.u32.u64 %0, t; }"
        : "=r"(a) : "l"(p));
    return a;
}
#define SW128(o) ((o) ^ (((o) >> 3) & 0x70))

#define CP_ASYNC16(dst, src) \
    asm volatile("cp.async.cg.shared.global [%0], [%1], 16;" \
                 :: "r"(dst), "l"(src) : "memory")
#define CP_COMMIT() asm volatile("cp.async.commit_group;" ::: "memory")
#define CP_WAIT0()  asm volatile("cp.async.wait_group 0;" ::: "memory")
#define CP_WAIT1()  asm volatile("cp.async.wait_group 1;" ::: "memory")

__device__ __forceinline__ void ldsm4(uint32_t* r, uint32_t addr) {
    asm volatile("ldmatrix.sync.aligned.m8n8.x4.shared.b16 {%0,%1,%2,%3}, [%4];"
        : "=r"(r[0]), "=r"(r[1]), "=r"(r[2]), "=r"(r[3]) : "r"(addr));
}
__device__ __forceinline__ void ldsm4t(uint32_t* r, uint32_t addr) {
    asm volatile("ldmatrix.sync.aligned.m8n8.x4.trans.shared.b16 {%0,%1,%2,%3}, [%4];"
        : "=r"(r[0]), "=r"(r[1]), "=r"(r[2]), "=r"(r[3]) : "r"(addr));
}
__device__ __forceinline__ void mma16816(float* d, const uint32_t* a,
                                         const uint32_t* b) {
    asm volatile(
        "mma.sync.aligned.m16n8k16.row.col.f32.bf16.bf16.f32 "
        "{%0,%1,%2,%3}, {%4,%5,%6,%7}, {%8,%9}, {%0,%1,%2,%3};"
        : "+f"(d[0]), "+f"(d[1]), "+f"(d[2]), "+f"(d[3])
        : "r"(a[0]), "r"(a[1]), "r"(a[2]), "r"(a[3]), "r"(b[0]), "r"(b[1]));
}
__device__ __forceinline__ uint32_t packbf(float x, float y) {
    __nv_bfloat162 t = __floats2bfloat162_rn(x, y);
    return *(uint32_t*)&t;
}

// ---------------------------------------------------------------------------
// mask prep: canonicalize dtype (bool/int32/f32) AND compact unmasked key
// indices per batch. grid = BB blocks x 1024 threads (one thread per key).
// Each block redundantly sniffs the full array (deterministic, cheap).
// g_idx[b][0..cnt-1] = original indices of unmasked keys; padding -> row 0.
// ---------------------------------------------------------------------------
__global__ __launch_bounds__(NN_) void mask_prep_kernel(
    const unsigned char* __restrict__ raw) {
    __shared__ int s_mis, s_notf, s_one;
    __shared__ int pre[NN_];
    const int tid = threadIdx.x;
    const int b = blockIdx.x;

    if (tid == 0) { s_mis = 0; s_notf = 0; s_one = 0; }
    __syncthreads();
    int mis = 0, notf = 0, one = 0;
    const int* ri = (const int*)raw;
    for (int i = tid; i < MTOT; i += NN_)
        if ((i & 3) != 0 && raw[i] != 0) mis = 1;
    for (int i = tid; i < MTOT / 4; i += NN_) {
        int v = ri[i];
        if (v == 0x3f800000) one = 1; else if (v != 0) notf = 1;
    }
    if (mis)  atomicOr(&s_mis, 1);
    if (notf) atomicOr(&s_notf, 1);
    if (one)  atomicOr(&s_one, 1);
    __syncthreads();
    const int is_f32 = (!s_notf) && s_one;
    const int is_i32 = (!is_f32) && (!s_mis);

    const int gi = b * NN_ + tid;
    unsigned char m;
    if (is_f32)      m = (((const float*)raw)[gi] != 0.0f) ? 1 : 0;
    else if (is_i32) m = (((const int*)raw)[gi]   != 0)    ? 1 : 0;
    else             m = (raw[gi] != 0) ? 1 : 0;
    const int keep = m ? 0 : 1;          // keep if NOT masked

    pre[tid] = keep;
    __syncthreads();
    // inclusive scan (Hillis-Steele)
    for (int off = 1; off < NN_; off <<= 1) {
        int v = (tid >= off) ? pre[tid - off] : 0;
        __syncthreads();
        pre[tid] += v;
        __syncthreads();
    }
    const int cnt = pre[NN_ - 1];
    if (keep) g_idx[b * NN_ + pre[tid] - 1] = tid;
    const int padded = ((cnt + 63) >> 6) << 6;
    if (tid >= cnt && tid < padded) g_idx[b * NN_ + tid] = 0;  // padding rows
    if (tid == 0) g_cnt[b] = cnt;
}

// ---------------------------------------------------------------------------
// split conversion: src[rows][768] f32 -> dst[rows][2304] bf16
// pattern 0 (A side): [hi, hi, lo] ; pattern 1 (B side): [hi, lo, hi]
// ---------------------------------------------------------------------------
template <int PAT>
__global__ void split_kernel(const float* __restrict__ src,
                             __nv_bfloat16* __restrict__ dst, int total) {
    int i = blockIdx.x * blockDim.x + threadIdx.x;
    if (i >= total) return;
    int m = i / DIM, k = i % DIM;
    float v = src[i];
    __nv_bfloat16 h = __float2bfloat16(v);
    __nv_bfloat16 l = __float2bfloat16(v - __bfloat162float(h));
    size_t base = (size_t)m * K2 + k;
    if (PAT == 0) { dst[base] = h; dst[base + DIM] = h; dst[base + 2 * DIM] = l; }
    else          { dst[base] = h; dst[base + DIM] = l; dst[base + 2 * DIM] = h; }
}

// ---------------------------------------------------------------------------
// mma.sync GEMM: C[M, Ntot] = A'[M,2304] @ B'[Ntot,2304]^T
// 2-stage cp.async pipeline, 2 CTAs/SM (regs capped at 128).  [R10, unchanged]
// MODE 0: out = C + bias_b[n]                         (projection)
// MODE 1: split-scatter to q/k/v hi-lo planes (+biases, q*scale)
// ---------------------------------------------------------------------------
#define TILE16K  16384
#define STAGE_B  (2 * TILE16K)
#define GEMM_DSMEM (2 * STAGE_B)       // 65536

template <int MODE>
__global__ __launch_bounds__(256, 2) void mma_gemm_kernel(
    const __nv_bfloat16* __restrict__ A2, const __nv_bfloat16* __restrict__ B2,
    const float* __restrict__ bias_a, const float* __restrict__ bias_b,
    float* __restrict__ out, int Ntot)
{
    extern __shared__ char sm[];
    const int tid  = threadIdx.x;
    const int lane = tid & 31;
    const int wid  = tid >> 5;
    const int wm   = wid & 3;
    const int wn   = wid >> 2;
    const int m0 = blockIdx.y * 128;
    const int n0 = blockIdx.x * 128;

    float acc[2][8][4];
#pragma unroll
    for (int a = 0; a < 2; a++)
#pragma unroll
        for (int b = 0; b < 8; b++)
#pragma unroll
            for (int c = 0; c < 4; c++) acc[a][b][c] = 0.f;

    auto load_tiles = [&](int kt, int s) {
        char* sa = sm + s * STAGE_B;
        char* sb = sa + TILE16K;
        const int k0 = kt * 64;
#pragma unroll
        for (int i = 0; i < 4; i++) {
            int idx = i * 256 + tid;
            int r = idx >> 3, ch = idx & 7;
            uint32_t dst = smem_u32(sa + SW128((uint32_t)(r * 128 + ch * 16)));
            CP_ASYNC16(dst, A2 + (size_t)(m0 + r) * K2 + k0 + ch * 8);
        }
#pragma unroll
        for (int i = 0; i < 4; i++) {
            int idx = i * 256 + tid;
            int r = idx >> 3, ch = idx & 7;
            uint32_t dst = smem_u32(sb + SW128((uint32_t)(r * 128 + ch * 16)));
            CP_ASYNC16(dst, B2 + (size_t)(n0 + r) * K2 + k0 + ch * 8);
        }
    };

    load_tiles(0, 0);
    CP_COMMIT();

    for (int kt = 0; kt < NC64; kt++) {
        const int s = kt & 1;
        if (kt + 1 < NC64) {
            load_tiles(kt + 1, s ^ 1);
            CP_COMMIT();
            CP_WAIT1();
        } else {
            CP_WAIT0();
        }
        __syncthreads();

        const uint32_t a_base = smem_u32(sm + s * STAGE_B);
        const uint32_t b_base = a_base + TILE16K;
#pragma unroll
        for (int ks = 0; ks < 4; ks++) {
            uint32_t afr[2][4];
#pragma unroll
            for (int mt = 0; mt < 2; mt++) {
                int row = wm * 32 + mt * 16 + (lane & 15);
                uint32_t off = SW128((uint32_t)(row * 128 + ks * 32
                                                + ((lane >> 4) << 4)));
                ldsm4(afr[mt], a_base + off);
            }
            uint32_t bfr[4][4];
#pragma unroll
            for (int p = 0; p < 4; p++) {
                int row = wn * 64 + p * 16 + ((lane >> 4) << 3) + (lane & 7);
                uint32_t off = SW128((uint32_t)(row * 128 + ks * 32
                                                + (((lane >> 3) & 1) << 4)));
                ldsm4(bfr[p], b_base + off);
            }
#pragma unroll
            for (int mt = 0; mt < 2; mt++)
#pragma unroll
                for (int p = 0; p < 4; p++) {
                    mma16816(acc[mt][2 * p + 0], afr[mt], &bfr[p][0]);
                    mma16816(acc[mt][2 * p + 1], afr[mt], &bfr[p][2]);
                }
        }
        __syncthreads();
    }

    // epilogue straight from registers
#pragma unroll
    for (int mt = 0; mt < 2; mt++) {
#pragma unroll
        for (int nt = 0; nt < 8; nt++) {
            int rb = m0 + wm * 32 + mt * 16 + (lane >> 2);
            int cb = n0 + wn * 64 + nt * 8 + ((lane & 3) << 1);
#pragma unroll
            for (int h2 = 0; h2 < 2; h2++) {
                int m = rb + h2 * 8;
                float v0 = acc[mt][nt][h2 * 2 + 0];
                float v1 = acc[mt][nt][h2 * 2 + 1];
                if (MODE == 0) {
                    float2 o = make_float2(v0 + bias_b[cb], v1 + bias_b[cb + 1]);
                    *(float2*)&out[(size_t)m * Ntot + cb] = o;
                } else {
                    int which = cb / DIM;
                    int cc = cb - which * DIM;
                    int h = cc >> 6, d = cc & 63;
                    int b = m >> 10, nn = m & 1023;
                    size_t dst = ((size_t)(b * NHEAD + h) * NN_ + nn) * HD + d;
                    if (which == 0) { v0 = (v0 + bias_a[cc]) * QKSCALE;
                                      v1 = (v1 + bias_a[cc + 1]) * QKSCALE; }
                    else if (which == 2) { v0 += bias_b[cc]; v1 += bias_b[cc + 1]; }
                    __nv_bfloat16 h0 = __float2bfloat16(v0);
                    __nv_bfloat16 h1 = __float2bfloat16(v1);
                    uint32_t lop = packbf(v0 - __bfloat162float(h0),
                                          v1 - __bfloat162float(h1));
                    uint32_t hp; { __nv_bfloat162 t; t.x = h0; t.y = h1;
                                   hp = *(uint32_t*)&t; }
                    __nv_bfloat16* ph; __nv_bfloat16* pl;
                    if (which == 0)      { ph = g_qh; pl = g_ql; }
                    else if (which == 1) { ph = g_kh; pl = g_kl; }
                    else                 { ph = g_vh; pl = g_vl; }
                    *(uint32_t*)&ph[dst] = hp;
                    *(uint32_t*)&pl[dst] = lop;
                }
            }
        }
    }
}

// ---------------------------------------------------------------------------
// Tensor-core flash attention over COMPACTED keys.
// CTA: 64 q-rows x 1 head, 4 warps. Key tile = 64 compacted keys, gathered
// through g_idx in load_kv. Loop runs ceil(cnt/64) tiles (~half of 16).
// S = Qh*Kh + Qh*Kl + Ql*Kh ; P split hi/lo ; O += Ph*Vh + Ph*Vl + Pl*Vh.
// ---------------------------------------------------------------------------
#define KT 64
#define ASTAGE 32768
#define ATTN_DSMEM (2 * ASTAGE)

__global__ __launch_bounds__(128) void attn_mma_kernel() {
    extern __shared__ char sm[];
    __shared__ float Ms[2][KT];

    const int tid  = threadIdx.x;
    const int lane = tid & 31;
    const int warp = tid >> 5;
    const int q0 = blockIdx.x * 64;
    const int bh = blockIdx.y;
    const int b  = bh / NHEAD;
    const size_t hbase = (size_t)bh * NN_ * HD;

    const __nv_bfloat16* qh_g = g_qh + hbase;
    const __nv_bfloat16* ql_g = g_ql + hbase;
    const __nv_bfloat16* kh_g = g_kh + hbase;
    const __nv_bfloat16* kl_g = g_kl + hbase;
    const __nv_bfloat16* vh_g = g_vh + hbase;
    const __nv_bfloat16* vl_g = g_vl + hbase;

    const int cnt = g_cnt[b];
    const int nkt = (cnt + 63) >> 6;          // >=1 for this workload
    const int* idxp = g_idx + b * NN_;

    // ---- stage Q (hi,lo) through smem, ldmatrix to registers ----
#pragma unroll
    for (int i = 0; i < 8; i++) {
        int idx = i * 128 + tid;               // 0..1023
        int arr = idx >> 9;                    // 0 hi, 1 lo
        int r = (idx >> 3) & 63, c = idx & 7;
        const __nv_bfloat16* src = (arr ? ql_g : qh_g) + (size_t)(q0 + r) * HD + c * 8;
        uint32_t dst = smem_u32(sm + arr * 8192 + SW128((uint32_t)(r * 128 + c * 16)));
        CP_ASYNC16(dst, src);
    }
    CP_COMMIT(); CP_WAIT0();
    __syncthreads();

    uint32_t qfh[4][4], qfl[4][4];
#pragma unroll
    for (int s = 0; s < 4; s++) {
        int row = warp * 16 + (lane & 15);
        uint32_t off = SW128((uint32_t)(row * 128 + s * 32 + ((lane >> 4) << 4)));
        ldsm4(qfh[s], smem_u32(sm) + off);
        ldsm4(qfl[s], smem_u32(sm) + 8192 + off);
    }
    __syncthreads();

    auto load_kv = [&](int t, int s) {
        int k0 = t * KT;
        char* st = sm + s * ASTAGE;
#pragma unroll
        for (int i = 0; i < 16; i++) {
            int idx = i * 128 + tid;           // 0..2047
            int arr = idx >> 9;                // 0 kh, 1 kl, 2 vh, 3 vl
            int r = (idx >> 3) & 63, c = idx & 7;
            int grow = idxp[k0 + r];           // gather through index map
            const __nv_bfloat16* bsrc =
                (arr == 0) ? kh_g : (arr == 1) ? kl_g : (arr == 2) ? vh_g : vl_g;
            uint32_t dst = smem_u32(st + arr * 8192 + SW128((uint32_t)(r * 128 + c * 16)));
            CP_ASYNC16(dst, bsrc + (size_t)grow * HD + c * 8);
        }
        if (tid < KT)
            Ms[s][tid] = (k0 + tid < cnt) ? 0.f : -1e30f;   // padding only
    };

    float m_[2] = {-1e30f, -1e30f};
    float l_[2] = {0.f, 0.f};
    float Oa[8][4];
#pragma unroll
    for (int j = 0; j < 8; j++)
#pragma unroll
        for (int c = 0; c < 4; c++) Oa[j][c] = 0.f;

    load_kv(0, 0);
    CP_COMMIT();

    for (int t = 0; t < nkt; t++) {
        const int s = t & 1;
        if (t + 1 < nkt) { load_kv(t + 1, s ^ 1); CP_COMMIT(); CP_WAIT1(); }
        else             { CP_WAIT0(); }
        __syncthreads();

        const uint32_t kh_b = smem_u32(sm + s * ASTAGE);
        const uint32_t kl_b = kh_b + 8192;
        const uint32_t vh_b = kh_b + 16384;
        const uint32_t vl_b = kh_b + 24576;

        // ---- S = Q K^T (3-term) ----
        float Sa[8][4];
#pragma unroll
        for (int j = 0; j < 8; j++)
#pragma unroll
            for (int c = 0; c < 4; c++) Sa[j][c] = 0.f;

#pragma unroll
        for (int sk = 0; sk < 4; sk++) {
            uint32_t bhf[4][4], blf[4][4];
#pragma unroll
            for (int p = 0; p < 4; p++) {
                int row = p * 16 + ((lane >> 4) << 3) + (lane & 7);
                uint32_t off = SW128((uint32_t)(row * 128 + sk * 32
                                                + (((lane >> 3) & 1) << 4)));
                ldsm4(bhf[p], kh_b + off);
                ldsm4(blf[p], kl_b + off);
            }
#pragma unroll
            for (int p = 0; p < 4; p++) {
                mma16816(Sa[2 * p + 0], qfh[sk], &bhf[p][0]);
                mma16816(Sa[2 * p + 1], qfh[sk], &bhf[p][2]);
                mma16816(Sa[2 * p + 0], qfh[sk], &blf[p][0]);
                mma16816(Sa[2 * p + 1], qfh[sk], &blf[p][2]);
                mma16816(Sa[2 * p + 0], qfl[sk], &bhf[p][0]);
                mma16816(Sa[2 * p + 1], qfl[sk], &bhf[p][2]);
            }
        }

        // ---- padding mask + online softmax ----
        const int cb = (lane & 3) << 1;
#pragma unroll
        for (int j = 0; j < 8; j++) {
            float2 ma = *(float2*)&Ms[s][j * 8 + cb];
            Sa[j][0] += ma.x; Sa[j][1] += ma.y;
            Sa[j][2] += ma.x; Sa[j][3] += ma.y;
        }
#pragma unroll
        for (int h = 0; h < 2; h++) {
            float mx = -1e30f;
#pragma unroll
            for (int j = 0; j < 8; j++)
                mx = fmaxf(mx, fmaxf(Sa[j][2 * h], Sa[j][2 * h + 1]));
            mx = fmaxf(mx, __shfl_xor_sync(0xffffffffu, mx, 1));
            mx = fmaxf(mx, __shfl_xor_sync(0xffffffffu, mx, 2));
            float mn = fmaxf(m_[h], mx);
            float corr = __expf(m_[h] - mn);
            m_[h] = mn;
            float rs = 0.f;
#pragma unroll
            for (int j = 0; j < 8; j++) {
                Sa[j][2 * h]     = __expf(Sa[j][2 * h]     - mn);
                Sa[j][2 * h + 1] = __expf(Sa[j][2 * h + 1] - mn);
                rs += Sa[j][2 * h] + Sa[j][2 * h + 1];
            }
            rs += __shfl_xor_sync(0xffffffffu, rs, 1);
            rs += __shfl_xor_sync(0xffffffffu, rs, 2);
            l_[h] = l_[h] * corr + rs;
#pragma unroll
            for (int j = 0; j < 8; j++) {
                Oa[j][2 * h]     *= corr;
                Oa[j][2 * h + 1] *= corr;
            }
        }

        // ---- O += P V (3-term), P repacked from S fragments ----
#pragma unroll
        for (int k2 = 0; k2 < 4; k2++) {
            uint32_t pah[4], pal[4];
#pragma unroll
            for (int u = 0; u < 2; u++) {
                int j = 2 * k2 + u;
                float p0 = Sa[j][0], p1 = Sa[j][1];
                float p2 = Sa[j][2], p3 = Sa[j][3];
                __nv_bfloat16 h0 = __float2bfloat16(p0), h1 = __float2bfloat16(p1);
                __nv_bfloat16 h2 = __float2bfloat16(p2), h3 = __float2bfloat16(p3);
                __nv_bfloat162 t0; t0.x = h0; t0.y = h1;
                __nv_bfloat162 t1; t1.x = h2; t1.y = h3;
                pah[u]     = *(uint32_t*)&t0;
                pah[u + 2] = *(uint32_t*)&t1;
                pal[u]     = packbf(p0 - __bfloat162float(h0),
                                    p1 - __bfloat162float(h1));
                pal[u + 2] = packbf(p2 - __bfloat162float(h2),
                                    p3 - __bfloat162float(h3));
            }
            // reorder to mma A-frag: {m0-7 k0-7, m8-15 k0-7, m0-7 k8-15, m8-15 k8-15}
            uint32_t pahf[4] = {pah[0], pah[2], pah[1], pah[3]};
            uint32_t palf[4] = {pal[0], pal[2], pal[1], pal[3]};
            uint32_t bvh[4][4], bvl[4][4];
#pragma unroll
            for (int p = 0; p < 4; p++) {
                int row = k2 * 16 + (lane & 15);
                uint32_t off = SW128((uint32_t)(row * 128 + p * 32
                                                + ((lane >> 4) << 4)));
                ldsm4t(bvh[p], vh_b + off);
                ldsm4t(bvl[p], vl_b + off);
            }
#pragma unroll
            for (int p = 0; p < 4; p++) {
                mma16816(Oa[2 * p + 0], pahf, &bvh[p][0]);
                mma16816(Oa[2 * p + 1], pahf, &bvh[p][2]);
                mma16816(Oa[2 * p + 0], pahf, &bvl[p][0]);
                mma16816(Oa[2 * p + 1], pahf, &bvl[p][2]);
                mma16816(Oa[2 * p + 0], palf, &bvh[p][0]);
                mma16816(Oa[2 * p + 1], palf, &bvh[p][2]);
            }
        }
        __syncthreads();
    }

    // ---- epilogue: normalize, split, write g_as ([hi,hi,lo] @ k,768+k,1536+k)
    const int hcol = (bh % NHEAD) * HD;
#pragma unroll
    for (int h = 0; h < 2; h++) {
        float inv = 1.f / l_[h];
        int row = q0 + warp * 16 + (lane >> 2) + h * 8;
        size_t mrow = (size_t)(b * NN_ + row) * K2;
#pragma unroll
        for (int j = 0; j < 8; j++) {
            int col = hcol + j * 8 + ((lane & 3) << 1);
            float v0 = Oa[j][2 * h] * inv;
            float v1 = Oa[j][2 * h + 1] * inv;
            __nv_bfloat16 h0 = __float2bfloat16(v0);
            __nv_bfloat16 h1 = __float2bfloat16(v1);
            __nv_bfloat162 hp; hp.x = h0; hp.y = h1;
            uint32_t lop = packbf(v0 - __bfloat162float(h0),
                                  v1 - __bfloat162float(h1));
            *(uint32_t*)&g_as[mrow + col]            = *(uint32_t*)&hp;
            *(uint32_t*)&g_as[mrow + DIM + col]      = *(uint32_t*)&hp;
            *(uint32_t*)&g_as[mrow + 2 * DIM + col]  = lop;
        }
    }
}

// ---------------------------------------------------------------------------
// launch
// ---------------------------------------------------------------------------
extern "C" void kernel_launch(void* const* d_in, const int* in_sizes, int n_in,
                              void* d_out, int out_size) {
    const float* x      = (const float*)d_in[0];
    const unsigned char* mask_raw = (const unsigned char*)d_in[1];
    const float* qkv_w  = (const float*)d_in[2];
    const float* q_bias = (const float*)d_in[3];
    const float* v_bias = (const float*)d_in[4];
    const float* proj_w = (const float*)d_in[5];
    const float* proj_b = (const float*)d_in[6];
    float* out          = (float*)d_out;
    (void)in_sizes; (void)n_in; (void)out_size;

    cudaFuncSetAttribute(mma_gemm_kernel<0>,
                         cudaFuncAttributeMaxDynamicSharedMemorySize, GEMM_DSMEM);
    cudaFuncSetAttribute(mma_gemm_kernel<1>,
                         cudaFuncAttributeMaxDynamicSharedMemorySize, GEMM_DSMEM);
    cudaFuncSetAttribute(attn_mma_kernel,
                         cudaFuncAttributeMaxDynamicSharedMemorySize, ATTN_DSMEM);

    __nv_bfloat16 *xs = nullptr, *ws = nullptr, *as = nullptr, *ps = nullptr;
    cudaGetSymbolAddress((void**)&xs, g_xs);
    cudaGetSymbolAddress((void**)&ws, g_ws);
    cudaGetSymbolAddress((void**)&as, g_as);
    cudaGetSymbolAddress((void**)&ps, g_ps);

    // 1) mask canonicalize + per-batch key compaction
    mask_prep_kernel<<<BB, NN_>>>(mask_raw);

    // 2) split conversions (x, qkv_w, proj_w)
    {
        int tA = MTOT * DIM;
        split_kernel<0><<<(tA + 255) / 256, 256>>>(x, xs, tA);
        int tB = 3 * DIM * DIM;
        split_kernel<1><<<(tB + 255) / 256, 256>>>(qkv_w, ws, tB);
        int tP = DIM * DIM;
        split_kernel<1><<<(tP + 255) / 256, 256>>>(proj_w, ps, tP);
    }

    // 3) QKV GEMM -> q/k/v bf16 hi-lo planes
    mma_gemm_kernel<1><<<dim3(3 * DIM / 128, MTOT / 128), 256, GEMM_DSMEM>>>(
        xs, ws, q_bias, v_bias, nullptr, 3 * DIM);

    // 4) tensor-core attention over compacted keys -> g_as
    attn_mma_kernel<<<dim3(NN_ / 64, BHTOT), 128, ATTN_DSMEM>>>();

    // 5) projection GEMM: [8192 x 768]
    mma_gemm_kernel<0><<<dim3(DIM / 128, MTOT / 128), 256, GEMM_DSMEM>>>(
        as, ps, nullptr, proj_b, out, DIM);
}